// round 13
// baseline (speedup 1.0000x reference)
#include <cuda_runtime.h>
#include <cuda_fp16.h>
#include <math.h>
#include <stdint.h>

#define N_NODES 4096
#define N_EDGES 16384
#define D_IN    128
#define HID     1024

// ---------------- scratch (device globals; no allocation allowed) ----------
// g_Ho / g_Hi invariant: zero at entry to every kernel_launch. They are
// zero-initialized at module load, and k_concat re-zeroes them after reading.
__device__ float g_Ho[N_NODES * D_IN];
__device__ float g_Hi[N_NODES * D_IN];
__device__ float g_h4[N_NODES * (HID / 4)];
// activations as single fp16 (round-to-nearest)
__device__ __half g_x [N_NODES * 3 * D_IN];
__device__ __half g_h1[N_NODES * HID];
__device__ __half g_h2[N_NODES * HID];
__device__ __half g_h3[N_NODES * (HID / 2)];
// transposed fp16 weights: [N,K] row-major
__device__ __half g_W1[HID * 3 * D_IN];
__device__ __half g_W2[HID * HID];
__device__ __half g_W3[(HID/2) * HID];
__device__ __half g_W4[(HID/4) * (HID/2)];

__device__ __forceinline__ float tanh_fast(float x) {
    float r;
    asm("tanh.approx.f32 %0, %1;" : "=f"(r) : "f"(x));
    return r;
}

#define REDV4(ptr, v) \
    asm volatile("red.global.add.v4.f32 [%0], {%1,%2,%3,%4};" \
                 :: "l"(ptr), "f"((v).x), "f"((v).y), "f"((v).z), "f"((v).w) : "memory")

// ---------------- fused kernel: one-hot scan + edge scatter ------------------
// One block per edge. Threads 0-127 scan Ro[e], threads 128-255 scan Ri[e],
// each half with independent early exit (named barriers). After the join,
// warp 0 scatters Ho[dst] += e[src]*H[src], warp 1 scatters Hi[src] += e[dst]*H[dst].
__global__ void __launch_bounds__(256)
k_edge(const float* __restrict__ Ro, const float* __restrict__ Ri,
       const float* __restrict__ H, const float* __restrict__ e) {
    __shared__ int col[2];
    int eidx = blockIdx.x;
    int tid = threadIdx.x;
    int half = tid >> 7;                 // 0: Ro, 1: Ri
    int t = tid & 127;
    const float* row = (half ? Ri : Ro) + (size_t)eidx * N_NODES;
    if (tid < 2) col[tid] = -1;
    __syncthreads();
    #pragma unroll 1
    for (int i = 0; i < 8; i++) {
        int v4 = t + i * 128;
        float4 v = ((const float4*)row)[v4];
        if (v.x != 0.f || v.y != 0.f || v.z != 0.f || v.w != 0.f) {
            int base = v4 * 4;
            col[half] = (v.x != 0.f) ? base : (v.y != 0.f) ? base + 1
                      : (v.z != 0.f) ? base + 2 : base + 3;
        }
        asm volatile("bar.sync %0, 128;" :: "r"(half + 1) : "memory");
        if (col[half] >= 0) break;
    }
    __syncthreads();                     // join: both indices found
    int s = col[0], d = col[1];
    if (tid < 32) {                      // Ho[dst] += e[src] * H[src]
        float es = e[s];
        float4 h = ((const float4*)(H + (size_t)s * D_IN))[tid];
        float4 v = make_float4(es * h.x, es * h.y, es * h.z, es * h.w);
        REDV4(g_Ho + (size_t)d * D_IN + tid * 4, v);
    } else if (tid < 64) {               // Hi[src] += e[dst] * H[dst]
        int l = tid - 32;
        float ed = e[d];
        float4 h = ((const float4*)(H + (size_t)d * D_IN))[l];
        float4 v = make_float4(ed * h.x, ed * h.y, ed * h.z, ed * h.w);
        REDV4(g_Hi + (size_t)s * D_IN + l * 4, v);
    }
}

// ---------------- concat: x = [Ho, H, Hi] -> fp16, then re-zero Ho/Hi --------
__global__ void k_concat(const float* __restrict__ H) {
    int idx = blockIdx.x * blockDim.x + threadIdx.x;
    const int per_row4 = 3 * D_IN / 4;
    const int total4 = N_NODES * per_row4;
    if (idx >= total4) return;
    int node = idx / per_row4;
    int c4 = idx - node * per_row4;
    float4 v;
    const float4 z = make_float4(0.f, 0.f, 0.f, 0.f);
    if (c4 < 32) {
        float4* p = (float4*)(g_Ho + (size_t)node * D_IN) + c4;
        v = *p; *p = z;                  // consume and re-zero for next launch
    } else if (c4 < 64) {
        v = ((const float4*)(H + (size_t)node * D_IN))[c4 - 32];
    } else {
        float4* p = (float4*)(g_Hi + (size_t)node * D_IN) + (c4 - 64);
        v = *p; *p = z;
    }
    __half2 p01 = __floats2half2_rn(v.x, v.y);
    __half2 p23 = __floats2half2_rn(v.z, v.w);
    size_t off = (size_t)node * (3 * D_IN) + c4 * 4;
    *(uint2*)(g_x + off) = make_uint2(*(uint32_t*)&p01, *(uint32_t*)&p23);
}

// ---------------- fused weight transpose + fp16 convert ----------------------
__device__ __forceinline__ void wconv_tile(const float* __restrict__ W,
                                           __half* __restrict__ O,
                                           int K, int N, int bx, int by,
                                           int x, int y, float t[32][33]) {
    #pragma unroll
    for (int j = 0; j < 32; j += 8)
        t[y + j][x] = W[(size_t)(by + y + j) * N + bx + x];
    __syncthreads();
    #pragma unroll
    for (int j = 0; j < 32; j += 8) {
        int n = bx + y + j, k = by + x;
        O[(size_t)n * K + k] = __float2half_rn(t[x][y + j]);
    }
}

__global__ void k_wconv_all(const float* __restrict__ W1, const float* __restrict__ W2,
                            const float* __restrict__ W3, const float* __restrict__ W4,
                            __half* w1, __half* w2, __half* w3, __half* w4) {
    __shared__ float t[32][33];
    int b = blockIdx.x;
    int x = threadIdx.x, y = threadIdx.y;
    if (b < 384) {
        wconv_tile(W1, w1, 3 * D_IN, HID, (b % 32) * 32, (b / 32) * 32, x, y, t);
    } else if (b < 1408) {
        b -= 384;
        wconv_tile(W2, w2, HID, HID, (b % 32) * 32, (b / 32) * 32, x, y, t);
    } else if (b < 1920) {
        b -= 1408;
        wconv_tile(W3, w3, HID, HID / 2, (b % 16) * 32, (b / 16) * 32, x, y, t);
    } else {
        b -= 1920;
        wconv_tile(W4, w4, HID / 2, HID / 4, (b % 8) * 32, (b / 8) * 32, x, y, t);
    }
}

// ---------------- pipelined mma.sync GEMM (fp16, 64x64 warp tiles) ----------
#define TILE_A 16384

__device__ __forceinline__ uint32_t smem_u32(const void* p) {
    uint32_t a;
    asm("{ .reg .u64 t; cvta.to.shared.u64 t, %1; cvt.u32.u64 %0, t; }" : "=r"(a) : "l"(p));
    return a;
}
#define SWZ(row, kg) (((row) << 7) + ((((kg) ^ ((row) & 7))) << 4))
#define CP_ASYNC16(dst, src) \
    asm volatile("cp.async.cg.shared.global [%0], [%1], 16;" :: "r"(dst), "l"(src))
#define CP_COMMIT() asm volatile("cp.async.commit_group;" ::: "memory")
#define CP_WAIT1()  asm volatile("cp.async.wait_group 1;" ::: "memory")
#define LDSM_X4(r0, r1, r2, r3, addr) \
    asm volatile("ldmatrix.sync.aligned.m8n8.x4.shared.b16 {%0,%1,%2,%3}, [%4];" \
                 : "=r"(r0), "=r"(r1), "=r"(r2), "=r"(r3) : "r"(addr))

__device__ __forceinline__ void mma_f16(float* c, const uint32_t* a, const uint32_t* b) {
    asm volatile(
        "mma.sync.aligned.m16n8k16.row.col.f32.f16.f16.f32 "
        "{%0,%1,%2,%3}, {%4,%5,%6,%7}, {%8,%9}, {%0,%1,%2,%3};"
        : "+f"(c[0]), "+f"(c[1]), "+f"(c[2]), "+f"(c[3])
        : "r"(a[0]), "r"(a[1]), "r"(a[2]), "r"(a[3]), "r"(b[0]), "r"(b[1]));
}

template <int BN, bool HALF_OUT>
__global__ void __launch_bounds__(128, 2)
k_gemm(const __half* __restrict__ A, const __half* __restrict__ B,
       const float* __restrict__ bias,
       __half* __restrict__ Ch, float* __restrict__ Cf, int N, int K) {
    constexpr int TILE_BB = BN * 128;
    constexpr int STAGE_B = TILE_A + TILE_BB;
    constexpr int OFF_B = TILE_A;
    constexpr int NJ = BN / 16;
    constexpr int B_ITERS = BN * 8 / 128;

    extern __shared__ char smem[];
    const uint32_t sb = smem_u32(smem);
    const int tid = threadIdx.x;
    const int wid = tid >> 5;
    const int lane = tid & 31;
    const int wm = wid & 1;
    const int wn = wid >> 1;
    const int bm0 = blockIdx.y * 128;
    const int bn0 = blockIdx.x * BN;
    const int nch = K >> 6;

    float acc[4][NJ][4];
    #pragma unroll
    for (int mt = 0; mt < 4; mt++)
        #pragma unroll
        for (int j = 0; j < NJ; j++)
            #pragma unroll
            for (int q = 0; q < 4; q++) acc[mt][j][q] = 0.f;

    auto issue = [&](int c, int buf) {
        uint32_t base = sb + buf * STAGE_B;
        int k0 = c << 6;
        #pragma unroll
        for (int i = 0; i < 8; i++) {
            int idx = tid + i * 128;
            int row = idx >> 3, kg = idx & 7;
            CP_ASYNC16(base + SWZ(row, kg), A + (size_t)(bm0 + row) * K + k0 + kg * 8);
        }
        #pragma unroll
        for (int i = 0; i < B_ITERS; i++) {
            int idx = tid + i * 128;
            int row = idx >> 3, kg = idx & 7;
            CP_ASYNC16(base + OFF_B + SWZ(row, kg), B + (size_t)(bn0 + row) * K + k0 + kg * 8);
        }
    };

    issue(0, 0); CP_COMMIT();
    issue(1, 1); CP_COMMIT();

    const int a_row = wm * 64 + (lane & 15);
    const int a_kg  = lane >> 4;
    const int b_row = wn * (BN / 2) + (lane & 7) + (lane >> 4) * 8;
    const int b_kg  = (lane >> 3) & 1;

    int buf = 0;
    for (int i = 0; i < nch; i++) {
        int c = i + 2;
        CP_WAIT1();
        __syncthreads();
        if (c < nch) issue(c, c % 3);
        CP_COMMIT();

        uint32_t sbase = sb + buf * STAGE_B;
        #pragma unroll
        for (int ks8 = 0; ks8 < 8; ks8 += 2) {
            uint32_t af[4][4], bf[NJ][2];
            #pragma unroll
            for (int mt = 0; mt < 4; mt++) {
                uint32_t ad = sbase + SWZ(a_row + mt * 16, a_kg + ks8);
                LDSM_X4(af[mt][0], af[mt][1], af[mt][2], af[mt][3], ad);
            }
            #pragma unroll
            for (int jp = 0; jp < NJ / 2; jp++) {
                uint32_t bd = sbase + OFF_B + SWZ(b_row + jp * 16, b_kg + ks8);
                LDSM_X4(bf[jp*2][0], bf[jp*2][1], bf[jp*2+1][0], bf[jp*2+1][1], bd);
            }
            #pragma unroll
            for (int mt = 0; mt < 4; mt++)
                #pragma unroll
                for (int j = 0; j < NJ; j++)
                    mma_f16(acc[mt][j], af[mt], bf[j]);
        }
        buf = (buf == 2) ? 0 : buf + 1;
    }

    // ---- epilogue: bias + tanh ----
    const int g = lane >> 2, tig = lane & 3;
    #pragma unroll
    for (int mt = 0; mt < 4; mt++) {
        int row0 = bm0 + wm * 64 + mt * 16 + g;
        #pragma unroll
        for (int j = 0; j < NJ; j++) {
            int col = bn0 + wn * (BN / 2) + j * 8 + tig * 2;
            float bc0 = __ldg(bias + col), bc1 = __ldg(bias + col + 1);
            float v00 = tanh_fast(acc[mt][j][0] + bc0);
            float v01 = tanh_fast(acc[mt][j][1] + bc1);
            float v10 = tanh_fast(acc[mt][j][2] + bc0);
            float v11 = tanh_fast(acc[mt][j][3] + bc1);
            if (HALF_OUT) {
                __half2 p0 = __floats2half2_rn(v00, v01);
                __half2 p1 = __floats2half2_rn(v10, v11);
                *(uint32_t*)(Ch + (size_t)row0 * N + col)       = *(uint32_t*)&p0;
                *(uint32_t*)(Ch + (size_t)(row0 + 8) * N + col) = *(uint32_t*)&p1;
            } else {
                *(float2*)(Cf + (size_t)row0 * N + col)       = make_float2(v00, v01);
                *(float2*)(Cf + (size_t)(row0 + 8) * N + col) = make_float2(v10, v11);
            }
        }
    }
}

// ---------------- final layer: sigmoid(h4 @ W5 + b5), N=1 -------------------
__global__ void k_final(const float* __restrict__ h4, const float* __restrict__ W5,
                        const float* __restrict__ b5, float* __restrict__ out) {
    int gtid = blockIdx.x * blockDim.x + threadIdx.x;
    int row = gtid >> 5;
    int lane = gtid & 31;
    if (row >= N_NODES) return;
    const float4* a = (const float4*)(h4 + (size_t)row * (HID / 4));
    const float4* w = (const float4*)W5;
    float s = 0.f;
    #pragma unroll
    for (int i = 0; i < 2; i++) {
        int v4 = lane + i * 32;
        float4 x = a[v4], y = w[v4];
        s += x.x * y.x + x.y * y.y + x.z * y.z + x.w * y.w;
    }
    #pragma unroll
    for (int o = 16; o; o >>= 1) s += __shfl_xor_sync(0xffffffffu, s, o);
    if (lane == 0) out[row] = 1.f / (1.f + expf(-(s + b5[0])));
}

// ---------------- launcher ---------------------------------------------------
extern "C" void kernel_launch(void* const* d_in, const int* in_sizes, int n_in,
                              void* d_out, int out_size) {
    const float* H  = (const float*)d_in[0];
    const float* Ro = (const float*)d_in[1];
    const float* Ri = (const float*)d_in[2];
    const float* e  = (const float*)d_in[3];
    const float* W1 = (const float*)d_in[4];   const float* b1 = (const float*)d_in[5];
    const float* W2 = (const float*)d_in[6];   const float* b2 = (const float*)d_in[7];
    const float* W3 = (const float*)d_in[8];   const float* b3 = (const float*)d_in[9];
    const float* W4 = (const float*)d_in[10];  const float* b4 = (const float*)d_in[11];
    const float* W5 = (const float*)d_in[12];  const float* b5 = (const float*)d_in[13];
    float* out = (float*)d_out;
    (void)in_sizes; (void)n_in; (void)out_size;

    __half *xp, *h1p, *h2p, *h3p, *w1, *w2, *w3, *w4;
    float* p_h4;
    cudaGetSymbolAddress((void**)&xp,  g_x);
    cudaGetSymbolAddress((void**)&h1p, g_h1);
    cudaGetSymbolAddress((void**)&h2p, g_h2);
    cudaGetSymbolAddress((void**)&h3p, g_h3);
    cudaGetSymbolAddress((void**)&p_h4, g_h4);
    cudaGetSymbolAddress((void**)&w1, g_W1);
    cudaGetSymbolAddress((void**)&w2, g_W2);
    cudaGetSymbolAddress((void**)&w3, g_W3);
    cudaGetSymbolAddress((void**)&w4, g_W4);

    const int SMEM128 = 3 * (TILE_A + 128 * 128);   // 96 KB
    const int SMEM64  = 3 * (TILE_A + 64 * 128);    // 72 KB
    cudaFuncSetAttribute(k_gemm<128, true>,  cudaFuncAttributeMaxDynamicSharedMemorySize, SMEM128);
    cudaFuncSetAttribute(k_gemm<64,  true>,  cudaFuncAttributeMaxDynamicSharedMemorySize, SMEM64);
    cudaFuncSetAttribute(k_gemm<64,  false>, cudaFuncAttributeMaxDynamicSharedMemorySize, SMEM64);

    // side stream + events (created once, reused; graph-capturable pattern)
    static cudaStream_t s_w = nullptr;
    static cudaEvent_t ev_fork = nullptr, ev_w = nullptr;
    if (!s_w) {
        cudaStreamCreateWithFlags(&s_w, cudaStreamNonBlocking);
        cudaEventCreateWithFlags(&ev_fork, cudaEventDisableTiming);
        cudaEventCreateWithFlags(&ev_w,    cudaEventDisableTiming);
    }

    // fork: weight conversion overlaps the one-hot scan
    cudaEventRecord(ev_fork, 0);
    cudaStreamWaitEvent(s_w, ev_fork, 0);
    k_wconv_all<<<2048, dim3(32, 8), 0, s_w>>>(W1, W2, W3, W4, w1, w2, w3, w4);
    cudaEventRecord(ev_w, s_w);

    // main chain: fused scan+scatter -> concat(+re-zero) -> GEMMs -> head
    k_edge<<<N_EDGES, 256>>>(Ro, Ri, H, e);
    k_concat<<<(N_NODES * 96 + 255) / 256, 256>>>(H);
    cudaStreamWaitEvent(0, ev_w, 0);

    k_gemm<128, true><<<dim3(HID / 128, N_NODES / 128), 128, SMEM128>>>(xp,  w1, b1, h1p, nullptr, HID,     3 * D_IN);
    k_gemm<128, true><<<dim3(HID / 128, N_NODES / 128), 128, SMEM128>>>(h1p, w2, b2, h2p, nullptr, HID,     HID);
    k_gemm<64,  true><<<dim3(HID / 2 / 64, N_NODES / 128), 128, SMEM64>>>(h2p, w3, b3, h3p, nullptr, HID / 2, HID);
    k_gemm<64, false><<<dim3(HID / 4 / 64, N_NODES / 128), 128, SMEM64>>>(h3p, w4, b4, nullptr, p_h4, HID / 4, HID / 2);
    k_final<<<(N_NODES * 32 + 255) / 256, 256>>>(p_h4, W5, b5, out);
}

// round 14
// speedup vs baseline: 1.3686x; 1.3686x over previous
#include <cuda_runtime.h>
#include <cuda_fp16.h>
#include <math.h>
#include <stdint.h>

#define N_NODES 4096
#define N_EDGES 16384
#define D_IN    128
#define HID     1024

// ---------------- scratch (device globals; no allocation allowed) ----------
// g_Ho / g_Hi invariant: zero at entry to every kernel_launch. Zeroed at
// module load; k_concat re-zeroes them after consuming.
__device__ float g_Ho[N_NODES * D_IN];
__device__ float g_Hi[N_NODES * D_IN];
__device__ int   g_src[N_EDGES];
__device__ int   g_dst[N_EDGES];
__device__ float g_h4[N_NODES * (HID / 4)];
// activations as single fp16 (round-to-nearest)
__device__ __half g_x [N_NODES * 3 * D_IN];
__device__ __half g_h1[N_NODES * HID];
__device__ __half g_h2[N_NODES * HID];
__device__ __half g_h3[N_NODES * (HID / 2)];
// transposed fp16 weights: [N,K] row-major
__device__ __half g_W1[HID * 3 * D_IN];
__device__ __half g_W2[HID * HID];
__device__ __half g_W3[(HID/2) * HID];
__device__ __half g_W4[(HID/4) * (HID/2)];

__device__ __forceinline__ float tanh_fast(float x) {
    float r;
    asm("tanh.approx.f32 %0, %1;" : "=f"(r) : "f"(x));
    return r;
}

// ---------------- kernel 1: one-hot -> index, with early exit ---------------
__global__ void k_extract(const float* __restrict__ Ro, const float* __restrict__ Ri) {
    __shared__ int found;
    int e = blockIdx.x;
    const float* row = (blockIdx.y == 0 ? Ro : Ri) + (size_t)e * N_NODES;
    int* out = (blockIdx.y == 0 ? g_src : g_dst);
    if (threadIdx.x == 0) found = 0;
    __syncthreads();
    int t = threadIdx.x;
    #pragma unroll 1
    for (int i = 0; i < 8; i++) {
        int v4 = t + i * 128;
        float4 v = ((const float4*)row)[v4];
        if (v.x != 0.f || v.y != 0.f || v.z != 0.f || v.w != 0.f) {
            int base = v4 * 4;
            int col = (v.x != 0.f) ? base : (v.y != 0.f) ? base + 1
                    : (v.z != 0.f) ? base + 2 : base + 3;
            out[e] = col;
            found = 1;
        }
        __syncthreads();
        if (found) return;
    }
}

// ---------------- kernel 2: edge scatter, e*H computed inline ----------------
#define REDV4(ptr, v) \
    asm volatile("red.global.add.v4.f32 [%0], {%1,%2,%3,%4};" \
                 :: "l"(ptr), "f"((v).x), "f"((v).y), "f"((v).z), "f"((v).w) : "memory")

__global__ void k_scatter(const float* __restrict__ H, const float* __restrict__ e) {
    int gtid = blockIdx.x * blockDim.x + threadIdx.x;
    int warp = gtid >> 5;
    int lane = gtid & 31;
    if (warp >= N_EDGES) return;
    int s = g_src[warp];
    int d = g_dst[warp];
    float es = e[s], ed = e[d];
    float4 hs = ((const float4*)(H + (size_t)s * D_IN))[lane];
    float4 hd = ((const float4*)(H + (size_t)d * D_IN))[lane];
    float4 vs = make_float4(es * hs.x, es * hs.y, es * hs.z, es * hs.w);
    float4 vd = make_float4(ed * hd.x, ed * hd.y, ed * hd.z, ed * hd.w);
    REDV4(g_Ho + (size_t)d * D_IN + lane * 4, vs);   // Ho[dst] += e[src]*H[src]
    REDV4(g_Hi + (size_t)s * D_IN + lane * 4, vd);   // Hi[src] += e[dst]*H[dst]
}

// ---------------- kernel 3: x = [Ho, H, Hi] -> fp16, re-zero Ho/Hi -----------
__global__ void k_concat(const float* __restrict__ H) {
    int idx = blockIdx.x * blockDim.x + threadIdx.x;
    const int per_row4 = 3 * D_IN / 4;
    const int total4 = N_NODES * per_row4;
    if (idx >= total4) return;
    int node = idx / per_row4;
    int c4 = idx - node * per_row4;
    float4 v;
    const float4 z = make_float4(0.f, 0.f, 0.f, 0.f);
    if (c4 < 32) {
        float4* p = (float4*)(g_Ho + (size_t)node * D_IN) + c4;
        v = *p; *p = z;                  // consume and re-zero for next launch
    } else if (c4 < 64) {
        v = ((const float4*)(H + (size_t)node * D_IN))[c4 - 32];
    } else {
        float4* p = (float4*)(g_Hi + (size_t)node * D_IN) + (c4 - 64);
        v = *p; *p = z;
    }
    __half2 p01 = __floats2half2_rn(v.x, v.y);
    __half2 p23 = __floats2half2_rn(v.z, v.w);
    size_t off = (size_t)node * (3 * D_IN) + c4 * 4;
    *(uint2*)(g_x + off) = make_uint2(*(uint32_t*)&p01, *(uint32_t*)&p23);
}

// ---------------- fused weight transpose + fp16 convert ----------------------
__device__ __forceinline__ void wconv_tile(const float* __restrict__ W,
                                           __half* __restrict__ O,
                                           int K, int N, int bx, int by,
                                           int x, int y, float t[32][33]) {
    #pragma unroll
    for (int j = 0; j < 32; j += 8)
        t[y + j][x] = W[(size_t)(by + y + j) * N + bx + x];
    __syncthreads();
    #pragma unroll
    for (int j = 0; j < 32; j += 8) {
        int n = bx + y + j, k = by + x;
        O[(size_t)n * K + k] = __float2half_rn(t[x][y + j]);
    }
}

__global__ void k_wconv_all(const float* __restrict__ W1, const float* __restrict__ W2,
                            const float* __restrict__ W3, const float* __restrict__ W4,
                            __half* w1, __half* w2, __half* w3, __half* w4) {
    __shared__ float t[32][33];
    int b = blockIdx.x;
    int x = threadIdx.x, y = threadIdx.y;
    if (b < 384) {
        wconv_tile(W1, w1, 3 * D_IN, HID, (b % 32) * 32, (b / 32) * 32, x, y, t);
    } else if (b < 1408) {
        b -= 384;
        wconv_tile(W2, w2, HID, HID, (b % 32) * 32, (b / 32) * 32, x, y, t);
    } else if (b < 1920) {
        b -= 1408;
        wconv_tile(W3, w3, HID, HID / 2, (b % 16) * 32, (b / 16) * 32, x, y, t);
    } else {
        b -= 1920;
        wconv_tile(W4, w4, HID / 2, HID / 4, (b % 8) * 32, (b / 8) * 32, x, y, t);
    }
}

// ---------------- pipelined mma.sync GEMM (fp16, 256 thr, 32x64 warp tiles) --
// A [M,K] fp16; B [N,K] fp16. CTA 128xBN, warp grid 4x2, K-chunk 64,
// 3-stage cp.async, single barrier per chunk, XOR-swizzled rows, fp32 acc.
#define TILE_A 16384

__device__ __forceinline__ uint32_t smem_u32(const void* p) {
    uint32_t a;
    asm("{ .reg .u64 t; cvta.to.shared.u64 t, %1; cvt.u32.u64 %0, t; }" : "=r"(a) : "l"(p));
    return a;
}
#define SWZ(row, kg) (((row) << 7) + ((((kg) ^ ((row) & 7))) << 4))
#define CP_ASYNC16(dst, src) \
    asm volatile("cp.async.cg.shared.global [%0], [%1], 16;" :: "r"(dst), "l"(src))
#define CP_COMMIT() asm volatile("cp.async.commit_group;" ::: "memory")
#define CP_WAIT1()  asm volatile("cp.async.wait_group 1;" ::: "memory")
#define LDSM_X4(r0, r1, r2, r3, addr) \
    asm volatile("ldmatrix.sync.aligned.m8n8.x4.shared.b16 {%0,%1,%2,%3}, [%4];" \
                 : "=r"(r0), "=r"(r1), "=r"(r2), "=r"(r3) : "r"(addr))

__device__ __forceinline__ void mma_f16(float* c, const uint32_t* a, const uint32_t* b) {
    asm volatile(
        "mma.sync.aligned.m16n8k16.row.col.f32.f16.f16.f32 "
        "{%0,%1,%2,%3}, {%4,%5,%6,%7}, {%8,%9}, {%0,%1,%2,%3};"
        : "+f"(c[0]), "+f"(c[1]), "+f"(c[2]), "+f"(c[3])
        : "r"(a[0]), "r"(a[1]), "r"(a[2]), "r"(a[3]), "r"(b[0]), "r"(b[1]));
}

template <int BN, bool HALF_OUT>
__global__ void __launch_bounds__(256, 2)
k_gemm(const __half* __restrict__ A, const __half* __restrict__ B,
       const float* __restrict__ bias,
       __half* __restrict__ Ch, float* __restrict__ Cf, int N, int K) {
    constexpr int TILE_BB = BN * 128;
    constexpr int STAGE_B = TILE_A + TILE_BB;
    constexpr int OFF_B = TILE_A;
    constexpr int NJ = BN / 16;
    constexpr int B_ITERS = BN / 32;

    extern __shared__ char smem[];
    const uint32_t sb = smem_u32(smem);
    const int tid = threadIdx.x;
    const int wid = tid >> 5;
    const int lane = tid & 31;
    const int wm = wid & 3;
    const int wn = wid >> 2;
    const int bm0 = blockIdx.y * 128;
    const int bn0 = blockIdx.x * BN;
    const int nch = K >> 6;

    float acc[2][NJ][4];
    #pragma unroll
    for (int mt = 0; mt < 2; mt++)
        #pragma unroll
        for (int j = 0; j < NJ; j++)
            #pragma unroll
            for (int q = 0; q < 4; q++) acc[mt][j][q] = 0.f;

    auto issue = [&](int c, int buf) {
        uint32_t base = sb + buf * STAGE_B;
        int k0 = c << 6;
        #pragma unroll
        for (int i = 0; i < 4; i++) {
            int idx = tid + i * 256;
            int row = idx >> 3, kg = idx & 7;
            CP_ASYNC16(base + SWZ(row, kg), A + (size_t)(bm0 + row) * K + k0 + kg * 8);
        }
        #pragma unroll
        for (int i = 0; i < B_ITERS; i++) {
            int idx = tid + i * 256;
            int row = idx >> 3, kg = idx & 7;
            CP_ASYNC16(base + OFF_B + SWZ(row, kg), B + (size_t)(bn0 + row) * K + k0 + kg * 8);
        }
    };

    issue(0, 0); CP_COMMIT();
    issue(1, 1); CP_COMMIT();

    const int a_row = wm * 32 + (lane & 15);
    const int a_kg  = lane >> 4;
    const int b_row = wn * (BN / 2) + (lane & 7) + (lane >> 4) * 8;
    const int b_kg  = (lane >> 3) & 1;

    int buf = 0;
    for (int i = 0; i < nch; i++) {
        int c = i + 2;
        CP_WAIT1();           // stage i resident
        __syncthreads();      // all warps done reading stage (i-1)%3
        if (c < nch) issue(c, c % 3);
        CP_COMMIT();          // one commit per iteration (empty ok)

        uint32_t sbase = sb + buf * STAGE_B;
        #pragma unroll
        for (int ks8 = 0; ks8 < 8; ks8 += 2) {
            uint32_t af[2][4], bf[NJ][2];
            #pragma unroll
            for (int mt = 0; mt < 2; mt++) {
                uint32_t ad = sbase + SWZ(a_row + mt * 16, a_kg + ks8);
                LDSM_X4(af[mt][0], af[mt][1], af[mt][2], af[mt][3], ad);
            }
            #pragma unroll
            for (int jp = 0; jp < NJ / 2; jp++) {
                uint32_t bd = sbase + OFF_B + SWZ(b_row + jp * 16, b_kg + ks8);
                LDSM_X4(bf[jp*2][0], bf[jp*2][1], bf[jp*2+1][0], bf[jp*2+1][1], bd);
            }
            #pragma unroll
            for (int mt = 0; mt < 2; mt++)
                #pragma unroll
                for (int j = 0; j < NJ; j++)
                    mma_f16(acc[mt][j], af[mt], bf[j]);
        }
        buf = (buf == 2) ? 0 : buf + 1;
    }

    // ---- epilogue: bias + tanh ----
    const int g = lane >> 2, tig = lane & 3;
    #pragma unroll
    for (int mt = 0; mt < 2; mt++) {
        int row0 = bm0 + wm * 32 + mt * 16 + g;
        #pragma unroll
        for (int j = 0; j < NJ; j++) {
            int col = bn0 + wn * (BN / 2) + j * 8 + tig * 2;
            float bc0 = __ldg(bias + col), bc1 = __ldg(bias + col + 1);
            float v00 = tanh_fast(acc[mt][j][0] + bc0);
            float v01 = tanh_fast(acc[mt][j][1] + bc1);
            float v10 = tanh_fast(acc[mt][j][2] + bc0);
            float v11 = tanh_fast(acc[mt][j][3] + bc1);
            if (HALF_OUT) {
                __half2 p0 = __floats2half2_rn(v00, v01);
                __half2 p1 = __floats2half2_rn(v10, v11);
                *(uint32_t*)(Ch + (size_t)row0 * N + col)       = *(uint32_t*)&p0;
                *(uint32_t*)(Ch + (size_t)(row0 + 8) * N + col) = *(uint32_t*)&p1;
            } else {
                *(float2*)(Cf + (size_t)row0 * N + col)       = make_float2(v00, v01);
                *(float2*)(Cf + (size_t)(row0 + 8) * N + col) = make_float2(v10, v11);
            }
        }
    }
}

// ---------------- final layer: sigmoid(h4 @ W5 + b5), N=1 -------------------
__global__ void k_final(const float* __restrict__ h4, const float* __restrict__ W5,
                        const float* __restrict__ b5, float* __restrict__ out) {
    int gtid = blockIdx.x * blockDim.x + threadIdx.x;
    int row = gtid >> 5;
    int lane = gtid & 31;
    if (row >= N_NODES) return;
    const float4* a = (const float4*)(h4 + (size_t)row * (HID / 4));
    const float4* w = (const float4*)W5;
    float s = 0.f;
    #pragma unroll
    for (int i = 0; i < 2; i++) {
        int v4 = lane + i * 32;
        float4 x = a[v4], y = w[v4];
        s += x.x * y.x + x.y * y.y + x.z * y.z + x.w * y.w;
    }
    #pragma unroll
    for (int o = 16; o; o >>= 1) s += __shfl_xor_sync(0xffffffffu, s, o);
    if (lane == 0) out[row] = 1.f / (1.f + expf(-(s + b5[0])));
}

// ---------------- launcher ---------------------------------------------------
extern "C" void kernel_launch(void* const* d_in, const int* in_sizes, int n_in,
                              void* d_out, int out_size) {
    const float* H  = (const float*)d_in[0];
    const float* Ro = (const float*)d_in[1];
    const float* Ri = (const float*)d_in[2];
    const float* e  = (const float*)d_in[3];
    const float* W1 = (const float*)d_in[4];   const float* b1 = (const float*)d_in[5];
    const float* W2 = (const float*)d_in[6];   const float* b2 = (const float*)d_in[7];
    const float* W3 = (const float*)d_in[8];   const float* b3 = (const float*)d_in[9];
    const float* W4 = (const float*)d_in[10];  const float* b4 = (const float*)d_in[11];
    const float* W5 = (const float*)d_in[12];  const float* b5 = (const float*)d_in[13];
    float* out = (float*)d_out;
    (void)in_sizes; (void)n_in; (void)out_size;

    __half *xp, *h1p, *h2p, *h3p, *w1, *w2, *w3, *w4;
    float* p_h4;
    cudaGetSymbolAddress((void**)&xp,  g_x);
    cudaGetSymbolAddress((void**)&h1p, g_h1);
    cudaGetSymbolAddress((void**)&h2p, g_h2);
    cudaGetSymbolAddress((void**)&h3p, g_h3);
    cudaGetSymbolAddress((void**)&p_h4, g_h4);
    cudaGetSymbolAddress((void**)&w1, g_W1);
    cudaGetSymbolAddress((void**)&w2, g_W2);
    cudaGetSymbolAddress((void**)&w3, g_W3);
    cudaGetSymbolAddress((void**)&w4, g_W4);

    const int SMEM128 = 3 * (TILE_A + 128 * 128);   // 96 KB
    const int SMEM64  = 3 * (TILE_A + 64 * 128);    // 72 KB
    cudaFuncSetAttribute(k_gemm<128, true>,  cudaFuncAttributeMaxDynamicSharedMemorySize, SMEM128);
    cudaFuncSetAttribute(k_gemm<64,  true>,  cudaFuncAttributeMaxDynamicSharedMemorySize, SMEM64);
    cudaFuncSetAttribute(k_gemm<64,  false>, cudaFuncAttributeMaxDynamicSharedMemorySize, SMEM64);

    // side stream + events (created once, reused; graph-capturable pattern)
    static cudaStream_t s_w = nullptr;
    static cudaEvent_t ev_fork = nullptr, ev_w = nullptr;
    if (!s_w) {
        cudaStreamCreateWithFlags(&s_w, cudaStreamNonBlocking);
        cudaEventCreateWithFlags(&ev_fork, cudaEventDisableTiming);
        cudaEventCreateWithFlags(&ev_w,    cudaEventDisableTiming);
    }

    // fork: weight conversion overlaps the one-hot scan
    cudaEventRecord(ev_fork, 0);
    cudaStreamWaitEvent(s_w, ev_fork, 0);
    k_wconv_all<<<2048, dim3(32, 8), 0, s_w>>>(W1, W2, W3, W4, w1, w2, w3, w4);
    cudaEventRecord(ev_w, s_w);

    // main chain: scan -> scatter (inline e*H) -> concat(+re-zero) -> GEMMs
    k_extract<<<dim3(N_EDGES, 2), 128>>>(Ro, Ri);
    k_scatter<<<(N_EDGES * 32 + 255) / 256, 256>>>(H, e);
    k_concat<<<(N_NODES * 96 + 255) / 256, 256>>>(H);
    cudaStreamWaitEvent(0, ev_w, 0);

    k_gemm<128, true><<<dim3(HID / 128, N_NODES / 128), 256, SMEM128>>>(xp,  w1, b1, h1p, nullptr, HID,     3 * D_IN);
    k_gemm<128, true><<<dim3(HID / 128, N_NODES / 128), 256, SMEM128>>>(h1p, w2, b2, h2p, nullptr, HID,     HID);
    k_gemm<64,  true><<<dim3(HID / 2 / 64, N_NODES / 128), 256, SMEM64>>>(h2p, w3, b3, h3p, nullptr, HID / 2, HID);
    k_gemm<64, false><<<dim3(HID / 4 / 64, N_NODES / 128), 256, SMEM64>>>(h3p, w4, b4, nullptr, p_h4, HID / 4, HID / 2);
    k_final<<<(N_NODES * 32 + 255) / 256, 256>>>(p_h4, W5, b5, out);
}

// round 16
// speedup vs baseline: 1.4352x; 1.0487x over previous
#include <cuda_runtime.h>
#include <cuda_fp16.h>
#include <math.h>
#include <stdint.h>

#define N_NODES 4096
#define N_EDGES 16384
#define D_IN    128
#define HID     1024

// ---------------- scratch (device globals; no allocation allowed) ----------
__device__ float g_Ho[N_NODES * D_IN];
__device__ float g_Hi[N_NODES * D_IN];
__device__ int   g_src[N_EDGES];
__device__ int   g_dst[N_EDGES];
__device__ float g_h4[N_NODES * (HID / 4)];
// activations as single fp16 (round-to-nearest)
__device__ __half g_x [N_NODES * 3 * D_IN];
__device__ __half g_h1[N_NODES * HID];
__device__ __half g_h2[N_NODES * HID];
__device__ __half g_h3[N_NODES * (HID / 2)];
// transposed fp16 weights: [N,K] row-major
__device__ __half g_W1[HID * 3 * D_IN];
__device__ __half g_W2[HID * HID];
__device__ __half g_W3[(HID/2) * HID];
__device__ __half g_W4[(HID/4) * (HID/2)];

__device__ __forceinline__ float tanh_fast(float x) {
    float r;
    asm("tanh.approx.f32 %0, %1;" : "=f"(r) : "f"(x));
    return r;
}

// ---------------- kernel 0: zero Ho/Hi (runs hidden under k_extract) --------
__global__ void k_zero() {
    int idx = blockIdx.x * blockDim.x + threadIdx.x;
    const int total4 = N_NODES * D_IN / 4;
    if (idx >= total4) return;
    const float4 z = make_float4(0.f, 0.f, 0.f, 0.f);
    ((float4*)g_Ho)[idx] = z;
    ((float4*)g_Hi)[idx] = z;
}

// ---------------- kernel 1: one-hot -> index, with early exit ---------------
__global__ void k_extract(const float* __restrict__ Ro, const float* __restrict__ Ri) {
    __shared__ int found;
    int e = blockIdx.x;
    const float* row = (blockIdx.y == 0 ? Ro : Ri) + (size_t)e * N_NODES;
    int* out = (blockIdx.y == 0 ? g_src : g_dst);
    if (threadIdx.x == 0) found = 0;
    __syncthreads();
    int t = threadIdx.x;
    #pragma unroll 1
    for (int i = 0; i < 8; i++) {
        int v4 = t + i * 128;
        float4 v = ((const float4*)row)[v4];
        if (v.x != 0.f || v.y != 0.f || v.z != 0.f || v.w != 0.f) {
            int base = v4 * 4;
            int col = (v.x != 0.f) ? base : (v.y != 0.f) ? base + 1
                    : (v.z != 0.f) ? base + 2 : base + 3;
            out[e] = col;
            found = 1;
        }
        __syncthreads();
        if (found) return;
    }
}

// ---------------- kernel 2: edge scatter, e*H computed inline ----------------
#define REDV4(ptr, v) \
    asm volatile("red.global.add.v4.f32 [%0], {%1,%2,%3,%4};" \
                 :: "l"(ptr), "f"((v).x), "f"((v).y), "f"((v).z), "f"((v).w) : "memory")

__global__ void k_scatter(const float* __restrict__ H, const float* __restrict__ e) {
    int gtid = blockIdx.x * blockDim.x + threadIdx.x;
    int warp = gtid >> 5;
    int lane = gtid & 31;
    if (warp >= N_EDGES) return;
    int s = g_src[warp];
    int d = g_dst[warp];
    float es = e[s], ed = e[d];
    float4 hs = ((const float4*)(H + (size_t)s * D_IN))[lane];
    float4 hd = ((const float4*)(H + (size_t)d * D_IN))[lane];
    float4 vs = make_float4(es * hs.x, es * hs.y, es * hs.z, es * hs.w);
    float4 vd = make_float4(ed * hd.x, ed * hd.y, ed * hd.z, ed * hd.w);
    REDV4(g_Ho + (size_t)d * D_IN + lane * 4, vs);   // Ho[dst] += e[src]*H[src]
    REDV4(g_Hi + (size_t)s * D_IN + lane * 4, vd);   // Hi[src] += e[dst]*H[dst]
}

// ---------------- kernel 3: x = [Ho, H, Hi] -> fp16 (pure read) --------------
__global__ void k_concat(const float* __restrict__ H) {
    int idx = blockIdx.x * blockDim.x + threadIdx.x;
    const int per_row4 = 3 * D_IN / 4;
    const int total4 = N_NODES * per_row4;
    if (idx >= total4) return;
    int node = idx / per_row4;
    int c4 = idx - node * per_row4;
    float4 v;
    if (c4 < 32)       v = ((const float4*)(g_Ho + (size_t)node * D_IN))[c4];
    else if (c4 < 64)  v = ((const float4*)(H    + (size_t)node * D_IN))[c4 - 32];
    else               v = ((const float4*)(g_Hi + (size_t)node * D_IN))[c4 - 64];
    __half2 p01 = __floats2half2_rn(v.x, v.y);
    __half2 p23 = __floats2half2_rn(v.z, v.w);
    size_t off = (size_t)node * (3 * D_IN) + c4 * 4;
    *(uint2*)(g_x + off) = make_uint2(*(uint32_t*)&p01, *(uint32_t*)&p23);
}

// ---------------- fused weight transpose + fp16 convert ----------------------
__device__ __forceinline__ void wconv_tile(const float* __restrict__ W,
                                           __half* __restrict__ O,
                                           int K, int N, int bx, int by,
                                           int x, int y, float t[32][33]) {
    #pragma unroll
    for (int j = 0; j < 32; j += 8)
        t[y + j][x] = W[(size_t)(by + y + j) * N + bx + x];
    __syncthreads();
    #pragma unroll
    for (int j = 0; j < 32; j += 8) {
        int n = bx + y + j, k = by + x;
        O[(size_t)n * K + k] = __float2half_rn(t[x][y + j]);
    }
}

__global__ void k_wconv_all(const float* __restrict__ W1, const float* __restrict__ W2,
                            const float* __restrict__ W3, const float* __restrict__ W4,
                            __half* w1, __half* w2, __half* w3, __half* w4) {
    __shared__ float t[32][33];
    int b = blockIdx.x;
    int x = threadIdx.x, y = threadIdx.y;
    if (b < 384) {
        wconv_tile(W1, w1, 3 * D_IN, HID, (b % 32) * 32, (b / 32) * 32, x, y, t);
    } else if (b < 1408) {
        b -= 384;
        wconv_tile(W2, w2, HID, HID, (b % 32) * 32, (b / 32) * 32, x, y, t);
    } else if (b < 1920) {
        b -= 1408;
        wconv_tile(W3, w3, HID, HID / 2, (b % 16) * 32, (b / 16) * 32, x, y, t);
    } else {
        b -= 1920;
        wconv_tile(W4, w4, HID / 2, HID / 4, (b % 8) * 32, (b / 8) * 32, x, y, t);
    }
}

// ---------------- pipelined mma.sync GEMM (fp16, 256 thr, 32x64 warp tiles) --
#define TILE_A 16384

__device__ __forceinline__ uint32_t smem_u32(const void* p) {
    uint32_t a;
    asm("{ .reg .u64 t; cvta.to.shared.u64 t, %1; cvt.u32.u64 %0, t; }" : "=r"(a) : "l"(p));
    return a;
}
#define SWZ(row, kg) (((row) << 7) + ((((kg) ^ ((row) & 7))) << 4))
#define CP_ASYNC16(dst, src) \
    asm volatile("cp.async.cg.shared.global [%0], [%1], 16;" :: "r"(dst), "l"(src))
#define CP_COMMIT() asm volatile("cp.async.commit_group;" ::: "memory")
#define CP_WAIT1()  asm volatile("cp.async.wait_group 1;" ::: "memory")
#define LDSM_X4(r0, r1, r2, r3, addr) \
    asm volatile("ldmatrix.sync.aligned.m8n8.x4.shared.b16 {%0,%1,%2,%3}, [%4];" \
                 : "=r"(r0), "=r"(r1), "=r"(r2), "=r"(r3) : "r"(addr))

__device__ __forceinline__ void mma_f16(float* c, const uint32_t* a, const uint32_t* b) {
    asm volatile(
        "mma.sync.aligned.m16n8k16.row.col.f32.f16.f16.f32 "
        "{%0,%1,%2,%3}, {%4,%5,%6,%7}, {%8,%9}, {%0,%1,%2,%3};"
        : "+f"(c[0]), "+f"(c[1]), "+f"(c[2]), "+f"(c[3])
        : "r"(a[0]), "r"(a[1]), "r"(a[2]), "r"(a[3]), "r"(b[0]), "r"(b[1]));
}

template <int BN, bool HALF_OUT>
__global__ void __launch_bounds__(256, 2)
k_gemm(const __half* __restrict__ A, const __half* __restrict__ B,
       const float* __restrict__ bias,
       __half* __restrict__ Ch, float* __restrict__ Cf, int N, int K) {
    constexpr int TILE_BB = BN * 128;
    constexpr int STAGE_B = TILE_A + TILE_BB;
    constexpr int OFF_B = TILE_A;
    constexpr int NJ = BN / 16;
    constexpr int B_ITERS = BN / 32;

    extern __shared__ char smem[];
    const uint32_t sb = smem_u32(smem);
    const int tid = threadIdx.x;
    const int wid = tid >> 5;
    const int lane = tid & 31;
    const int wm = wid & 3;
    const int wn = wid >> 2;
    const int bm0 = blockIdx.y * 128;
    const int bn0 = blockIdx.x * BN;
    const int nch = K >> 6;

    float acc[2][NJ][4];
    #pragma unroll
    for (int mt = 0; mt < 2; mt++)
        #pragma unroll
        for (int j = 0; j < NJ; j++)
            #pragma unroll
            for (int q = 0; q < 4; q++) acc[mt][j][q] = 0.f;

    auto issue = [&](int c, int buf) {
        uint32_t base = sb + buf * STAGE_B;
        int k0 = c << 6;
        #pragma unroll
        for (int i = 0; i < 4; i++) {
            int idx = tid + i * 256;
            int row = idx >> 3, kg = idx & 7;
            CP_ASYNC16(base + SWZ(row, kg), A + (size_t)(bm0 + row) * K + k0 + kg * 8);
        }
        #pragma unroll
        for (int i = 0; i < B_ITERS; i++) {
            int idx = tid + i * 256;
            int row = idx >> 3, kg = idx & 7;
            CP_ASYNC16(base + OFF_B + SWZ(row, kg), B + (size_t)(bn0 + row) * K + k0 + kg * 8);
        }
    };

    issue(0, 0); CP_COMMIT();
    issue(1, 1); CP_COMMIT();

    const int a_row = wm * 32 + (lane & 15);
    const int a_kg  = lane >> 4;
    const int b_row = wn * (BN / 2) + (lane & 7) + (lane >> 4) * 8;
    const int b_kg  = (lane >> 3) & 1;

    int buf = 0;
    for (int i = 0; i < nch; i++) {
        int c = i + 2;
        CP_WAIT1();           // stage i resident
        __syncthreads();      // all warps done reading stage (i-1)%3
        if (c < nch) issue(c, c % 3);
        CP_COMMIT();          // one commit per iteration (empty ok)

        uint32_t sbase = sb + buf * STAGE_B;
        #pragma unroll
        for (int ks8 = 0; ks8 < 8; ks8 += 2) {
            uint32_t af[2][4], bf[NJ][2];
            #pragma unroll
            for (int mt = 0; mt < 2; mt++) {
                uint32_t ad = sbase + SWZ(a_row + mt * 16, a_kg + ks8);
                LDSM_X4(af[mt][0], af[mt][1], af[mt][2], af[mt][3], ad);
            }
            #pragma unroll
            for (int jp = 0; jp < NJ / 2; jp++) {
                uint32_t bd = sbase + OFF_B + SWZ(b_row + jp * 16, b_kg + ks8);
                LDSM_X4(bf[jp*2][0], bf[jp*2][1], bf[jp*2+1][0], bf[jp*2+1][1], bd);
            }
            #pragma unroll
            for (int mt = 0; mt < 2; mt++)
                #pragma unroll
                for (int j = 0; j < NJ; j++)
                    mma_f16(acc[mt][j], af[mt], bf[j]);
        }
        buf = (buf == 2) ? 0 : buf + 1;
    }

    // ---- epilogue: bias + tanh ----
    const int g = lane >> 2, tig = lane & 3;
    #pragma unroll
    for (int mt = 0; mt < 2; mt++) {
        int row0 = bm0 + wm * 32 + mt * 16 + g;
        #pragma unroll
        for (int j = 0; j < NJ; j++) {
            int col = bn0 + wn * (BN / 2) + j * 8 + tig * 2;
            float bc0 = __ldg(bias + col), bc1 = __ldg(bias + col + 1);
            float v00 = tanh_fast(acc[mt][j][0] + bc0);
            float v01 = tanh_fast(acc[mt][j][1] + bc1);
            float v10 = tanh_fast(acc[mt][j][2] + bc0);
            float v11 = tanh_fast(acc[mt][j][3] + bc1);
            if (HALF_OUT) {
                __half2 p0 = __floats2half2_rn(v00, v01);
                __half2 p1 = __floats2half2_rn(v10, v11);
                *(uint32_t*)(Ch + (size_t)row0 * N + col)       = *(uint32_t*)&p0;
                *(uint32_t*)(Ch + (size_t)(row0 + 8) * N + col) = *(uint32_t*)&p1;
            } else {
                *(float2*)(Cf + (size_t)row0 * N + col)       = make_float2(v00, v01);
                *(float2*)(Cf + (size_t)(row0 + 8) * N + col) = make_float2(v10, v11);
            }
        }
    }
}

// ---------------- final layer: sigmoid(h4 @ W5 + b5), N=1 -------------------
__global__ void k_final(const float* __restrict__ h4, const float* __restrict__ W5,
                        const float* __restrict__ b5, float* __restrict__ out) {
    int gtid = blockIdx.x * blockDim.x + threadIdx.x;
    int row = gtid >> 5;
    int lane = gtid & 31;
    if (row >= N_NODES) return;
    const float4* a = (const float4*)(h4 + (size_t)row * (HID / 4));
    const float4* w = (const float4*)W5;
    float s = 0.f;
    #pragma unroll
    for (int i = 0; i < 2; i++) {
        int v4 = lane + i * 32;
        float4 x = a[v4], y = w[v4];
        s += x.x * y.x + x.y * y.y + x.z * y.z + x.w * y.w;
    }
    #pragma unroll
    for (int o = 16; o; o >>= 1) s += __shfl_xor_sync(0xffffffffu, s, o);
    if (lane == 0) out[row] = 1.f / (1.f + expf(-(s + b5[0])));
}

// ---------------- launcher ---------------------------------------------------
extern "C" void kernel_launch(void* const* d_in, const int* in_sizes, int n_in,
                              void* d_out, int out_size) {
    const float* H  = (const float*)d_in[0];
    const float* Ro = (const float*)d_in[1];
    const float* Ri = (const float*)d_in[2];
    const float* e  = (const float*)d_in[3];
    const float* W1 = (const float*)d_in[4];   const float* b1 = (const float*)d_in[5];
    const float* W2 = (const float*)d_in[6];   const float* b2 = (const float*)d_in[7];
    const float* W3 = (const float*)d_in[8];   const float* b3 = (const float*)d_in[9];
    const float* W4 = (const float*)d_in[10];  const float* b4 = (const float*)d_in[11];
    const float* W5 = (const float*)d_in[12];  const float* b5 = (const float*)d_in[13];
    float* out = (float*)d_out;
    (void)in_sizes; (void)n_in; (void)out_size;

    __half *xp, *h1p, *h2p, *h3p, *w1, *w2, *w3, *w4;
    float* p_h4;
    cudaGetSymbolAddress((void**)&xp,  g_x);
    cudaGetSymbolAddress((void**)&h1p, g_h1);
    cudaGetSymbolAddress((void**)&h2p, g_h2);
    cudaGetSymbolAddress((void**)&h3p, g_h3);
    cudaGetSymbolAddress((void**)&p_h4, g_h4);
    cudaGetSymbolAddress((void**)&w1, g_W1);
    cudaGetSymbolAddress((void**)&w2, g_W2);
    cudaGetSymbolAddress((void**)&w3, g_W3);
    cudaGetSymbolAddress((void**)&w4, g_W4);

    const int SMEM128 = 3 * (TILE_A + 128 * 128);   // 96 KB
    const int SMEM64  = 3 * (TILE_A + 64 * 128);    // 72 KB
    cudaFuncSetAttribute(k_gemm<128, true>,  cudaFuncAttributeMaxDynamicSharedMemorySize, SMEM128);
    cudaFuncSetAttribute(k_gemm<64,  true>,  cudaFuncAttributeMaxDynamicSharedMemorySize, SMEM64);
    cudaFuncSetAttribute(k_gemm<64,  false>, cudaFuncAttributeMaxDynamicSharedMemorySize, SMEM64);

    // side streams + events (created once, reused; graph-capturable pattern)
    static cudaStream_t s_w = nullptr, s_p = nullptr;
    static cudaEvent_t ev_fork = nullptr, ev_w = nullptr, ev_p = nullptr;
    if (!s_w) {
        cudaStreamCreateWithFlags(&s_w, cudaStreamNonBlocking);
        cudaStreamCreateWithFlags(&s_p, cudaStreamNonBlocking);
        cudaEventCreateWithFlags(&ev_fork, cudaEventDisableTiming);
        cudaEventCreateWithFlags(&ev_w,    cudaEventDisableTiming);
        cudaEventCreateWithFlags(&ev_p,    cudaEventDisableTiming);
    }

    // fork: weight conversion + Ho/Hi zeroing hidden under the one-hot scan
    cudaEventRecord(ev_fork, 0);
    cudaStreamWaitEvent(s_w, ev_fork, 0);
    cudaStreamWaitEvent(s_p, ev_fork, 0);
    k_wconv_all<<<2048, dim3(32, 8), 0, s_w>>>(W1, W2, W3, W4, w1, w2, w3, w4);
    cudaEventRecord(ev_w, s_w);
    k_zero<<<(N_NODES * D_IN / 4 + 255) / 256, 256, 0, s_p>>>();
    cudaEventRecord(ev_p, s_p);

    // main chain: scan -> scatter (inline e*H) -> concat -> GEMMs -> head
    k_extract<<<dim3(N_EDGES, 2), 128>>>(Ro, Ri);
    cudaStreamWaitEvent(0, ev_p, 0);          // scatter needs zeroed Ho/Hi
    k_scatter<<<(N_EDGES * 32 + 255) / 256, 256>>>(H, e);
    k_concat<<<(N_NODES * 96 + 255) / 256, 256>>>(H);
    cudaStreamWaitEvent(0, ev_w, 0);          // GEMMs need converted weights

    k_gemm<128, true><<<dim3(HID / 128, N_NODES / 128), 256, SMEM128>>>(xp,  w1, b1, h1p, nullptr, HID,     3 * D_IN);
    k_gemm<128, true><<<dim3(HID / 128, N_NODES / 128), 256, SMEM128>>>(h1p, w2, b2, h2p, nullptr, HID,     HID);
    k_gemm<64,  true><<<dim3(HID / 2 / 64, N_NODES / 128), 256, SMEM64>>>(h2p, w3, b3, h3p, nullptr, HID / 2, HID);
    k_gemm<64, false><<<dim3(HID / 4 / 64, N_NODES / 128), 256, SMEM64>>>(h3p, w4, b4, nullptr, p_h4, HID / 4, HID / 2);
    k_final<<<(N_NODES * 32 + 255) / 256, 256>>>(p_h4, W5, b5, out);
}